// round 1
// baseline (speedup 1.0000x reference)
#include <cuda_runtime.h>
#include <math.h>
#include <stddef.h>

#define N_ENT 2048
#define MENT  64
#define KCAND 32
#define LT 32
#define LB 128
#define LC 128
#define LD 512
#define VOCAB 5053
#define EMB 300
#define HDIM 256
#define HH 128
#define CCS 512
#define WIN 5
#define NSEQ 193   /* 64 title + 64 body + 64 ctx + 1 doc */
#define TT 32
#define G4 512     /* 4*HH */

/* ------------------------- scratch (device globals) ------------------------ */
__device__ float d_T[(size_t)VOCAB * WIN * CCS];      /* [v][w][c]  51.7MB */
__device__ float d_Bmat[EMB * WIN * CCS];             /* [e][(w,c)] */
__device__ float d_titleF[N_ENT * CCS];
__device__ float d_bodyF[N_ENT * CCS];
__device__ float d_ctxF[MENT * CCS];
__device__ float d_docF[CCS];
__device__ float d_X[NSEQ * TT * CCS];
__device__ float d_WihT_f[CCS * G4];
__device__ float d_WihT_b[CCS * G4];
__device__ float d_preF[NSEQ * TT * G4];
__device__ float d_preB[NSEQ * TT * G4];
__device__ float d_WhhT_f[HH * G4];
__device__ float d_WhhT_b[HH * G4];
__device__ float d_Hcat[NSEQ * TT * HDIM];
__device__ float d_p[2 * MENT * KCAND];

__device__ __forceinline__ float sigm(float x) { return 1.f / (1.f + expf(-x)); }

/* --------------------------- small transposes ----------------------------- */
__global__ void transpose_convw(const float* __restrict__ conv_w) {
    int idx = blockIdx.x * blockDim.x + threadIdx.x;
    int n = CCS * EMB * WIN;
    if (idx >= n) return;
    int c = idx / (EMB * WIN);
    int rem = idx % (EMB * WIN);
    int e = rem / WIN;
    int w = rem % WIN;
    d_Bmat[e * (WIN * CCS) + w * CCS + c] = conv_w[idx];
}

__global__ void transpose_wih(const float* __restrict__ Wih, int sel) {
    int idx = blockIdx.x * blockDim.x + threadIdx.x;
    int n = G4 * CCS;
    if (idx >= n) return;
    int g = idx / CCS;
    int k = idx % CCS;
    float* dst = sel ? d_WihT_b : d_WihT_f;
    dst[k * G4 + g] = Wih[idx];
}

__global__ void transpose_whh(const float* __restrict__ Whh, int sel) {
    int idx = blockIdx.x * blockDim.x + threadIdx.x;
    int n = G4 * HH;
    if (idx >= n) return;
    int g = idx / HH;
    int j = idx % HH;
    float* dst = sel ? d_WhhT_b : d_WhhT_f;
    dst[j * G4 + g] = Whh[idx];
}

/* ------------------------------ fp32 GEMM ---------------------------------- */
/* C[M,N] = A[M,K] @ B[K,N], row-major. BM=BN=64, BK=16, 256 thr, 4x4/thread. */
__global__ void sgemm(const float* __restrict__ A, const float* __restrict__ B,
                      float* __restrict__ C, int M, int N, int K) {
    __shared__ float As[16][65];
    __shared__ float Bs[16][65];
    int tid = threadIdx.x;
    int tx = tid & 15, ty = tid >> 4;
    int m0 = blockIdx.y * 64, n0 = blockIdx.x * 64;
    float acc[4][4] = {};
    for (int k0 = 0; k0 < K; k0 += 16) {
#pragma unroll
        for (int r = 0; r < 4; r++) {
            int li = tid * 4 + r;
            int m = li >> 4, kk = li & 15;
            float v = 0.f;
            if (m0 + m < M && k0 + kk < K) v = A[(size_t)(m0 + m) * K + k0 + kk];
            As[kk][m] = v;
        }
#pragma unroll
        for (int r = 0; r < 4; r++) {
            int li = tid * 4 + r;
            int kk = li >> 6, nn = li & 63;
            float v = 0.f;
            if (k0 + kk < K && n0 + nn < N) v = B[(size_t)(k0 + kk) * N + n0 + nn];
            Bs[kk][nn] = v;
        }
        __syncthreads();
#pragma unroll
        for (int kk = 0; kk < 16; kk++) {
            float ra[4], rb[4];
#pragma unroll
            for (int i = 0; i < 4; i++) ra[i] = As[kk][ty * 4 + i];
#pragma unroll
            for (int j = 0; j < 4; j++) rb[j] = Bs[kk][tx * 4 + j];
#pragma unroll
            for (int i = 0; i < 4; i++)
#pragma unroll
                for (int j = 0; j < 4; j++) acc[i][j] += ra[i] * rb[j];
        }
        __syncthreads();
    }
#pragma unroll
    for (int i = 0; i < 4; i++)
#pragma unroll
        for (int j = 0; j < 4; j++) {
            int m = m0 + ty * 4 + i, n = n0 + tx * 4 + j;
            if (m < M && n < N) C[(size_t)m * N + n] = acc[i][j];
        }
}

/* -------------------- conv via token table + maxpool ----------------------- */
/* feat[n][c] = max_p relu(bias[c] + sum_w T[tok[n,p+w]][w][c]) */
__global__ void conv_kernel(const int* __restrict__ toks, int L, int which,
                            const float* __restrict__ bias) {
    float* out = which == 0 ? d_titleF : which == 1 ? d_bodyF
               : which == 2 ? d_ctxF : d_docF;
    int n = blockIdx.x;
    int c = threadIdx.x;  /* 512 */
    __shared__ int st[LD];
    for (int i = c; i < L; i += CCS) st[i] = toks[(size_t)n * L + i];
    __syncthreads();
    float b = bias[c];
    float m = 0.f;
    int P = L - WIN + 1;
    for (int p = 0; p < P; p++) {
        float acc = b;
#pragma unroll
        for (int w = 0; w < WIN; w++) {
            int v = st[p + w];
            acc += d_T[((size_t)v * WIN + w) * CCS + c];
        }
        m = fmaxf(m, acc);
    }
    out[(size_t)n * CCS + c] = m;
}

/* -------------------------- gather LSTM inputs ----------------------------- */
__global__ void gatherX(const int* __restrict__ cand) {
    int idx = blockIdx.x * blockDim.x + threadIdx.x;
    int n = NSEQ * TT * CCS;
    if (idx >= n) return;
    int seq = idx / (TT * CCS);
    int r = idx % (TT * CCS);
    int t = r / CCS;
    int c = r % CCS;
    float v;
    if (seq < 64)       v = d_titleF[(size_t)cand[seq * TT + t] * CCS + c];
    else if (seq < 128) v = d_bodyF[(size_t)cand[(seq - 64) * TT + t] * CCS + c];
    else if (seq < 192) v = d_ctxF[(seq - 128) * CCS + c];
    else                v = d_docF[c];
    d_X[idx] = v;
}

/* ----------------------------- LSTM recurrence ----------------------------- */
/* grid (ceil(193/4), 2), 512 threads. 4 sequences per block per direction.   */
__global__ void lstm_kernel(const float* __restrict__ bih_f, const float* __restrict__ bhh_f,
                            const float* __restrict__ bih_b, const float* __restrict__ bhh_b) {
    int dir = blockIdx.y;
    int s0 = blockIdx.x * 4;
    const float* pre = dir ? d_preB : d_preF;
    const float* WT  = dir ? d_WhhT_b : d_WhhT_f;
    int g = threadIdx.x;  /* 0..511 */
    float bias = dir ? (bih_b[g] + bhh_b[g]) : (bih_f[g] + bhh_f[g]);
    __shared__ float sh[4][HH];
    __shared__ float scst[4][HH];
    __shared__ float sg[4][G4];
    {
        int s = g >> 7, d = g & 127;
        sh[s][d] = 0.f;
        scst[s][d] = 0.f;
    }
    __syncthreads();
    int nv = NSEQ - s0; if (nv > 4) nv = 4;
    for (int step = 0; step < TT; step++) {
        int t = dir ? (TT - 1 - step) : step;
        float a0 = (0 < nv) ? pre[((size_t)(s0 + 0) * TT + t) * G4 + g] + bias : 0.f;
        float a1 = (1 < nv) ? pre[((size_t)(s0 + 1) * TT + t) * G4 + g] + bias : 0.f;
        float a2 = (2 < nv) ? pre[((size_t)(s0 + 2) * TT + t) * G4 + g] + bias : 0.f;
        float a3 = (3 < nv) ? pre[((size_t)(s0 + 3) * TT + t) * G4 + g] + bias : 0.f;
#pragma unroll 8
        for (int j = 0; j < HH; j++) {
            float wv = WT[j * G4 + g];
            a0 += wv * sh[0][j];
            a1 += wv * sh[1][j];
            a2 += wv * sh[2][j];
            a3 += wv * sh[3][j];
        }
        sg[0][g] = a0; sg[1][g] = a1; sg[2][g] = a2; sg[3][g] = a3;
        __syncthreads();
        int s = g >> 7, d = g & 127;
        if (s < nv) {
            float iv = sg[s][d];
            float fv = sg[s][d + HH];
            float gv = sg[s][d + 2 * HH];
            float ov = sg[s][d + 3 * HH];
            float cn = sigm(fv) * scst[s][d] + sigm(iv) * tanhf(gv);
            float hn = sigm(ov) * tanhf(cn);
            scst[s][d] = cn;
            sh[s][d] = hn;
            d_Hcat[((size_t)(s0 + s) * TT + t) * HDIM + dir * HH + d] = hn;
        }
        __syncthreads();
    }
}

/* ------------------------------ BiDAF + score ------------------------------ */
/* grid (64 mentions, 2 pairs), 256 threads. pair0:(ctx,title)->p1 pair1:(doc,body)->p2 */
__global__ void att_kernel(const float* __restrict__ wc, const float* __restrict__ bc,
                           const float* __restrict__ wq, const float* __restrict__ bq,
                           const float* __restrict__ wcq, const float* __restrict__ bcq,
                           const float* __restrict__ wz, const float* __restrict__ bz) {
    int b = blockIdx.x;
    int pair = blockIdx.y;
    int tid = threadIdx.x;
    int cseq = pair ? 192 : 128 + b;
    int qseq = pair ? 64 + b : b;
    const float* Cg = d_Hcat + (size_t)cseq * TT * HDIM;
    const float* Qg = d_Hcat + (size_t)qseq * TT * HDIM;
    __shared__ float CS[TT * HDIM];
    __shared__ float S[TT * TT];
    __shared__ float Aw[TT * TT];
    __shared__ float CD[TT], QD[TT], SMX[TT], BV[TT];
    __shared__ float Q2C[HDIM];
    __shared__ float RED[8];
    for (int i = tid; i < TT * HDIM; i += 256) CS[i] = Cg[i];
    __syncthreads();
    if (tid < TT) {
        float s = 0.f;
        const float* crow = CS + tid * HDIM;
        for (int d = 0; d < HDIM; d++) s += crow[d] * wc[d];
        CD[tid] = s;
    } else if (tid < 2 * TT) {
        int j = tid - TT;
        float s = 0.f;
        const float* qrow = Qg + (size_t)j * HDIM;
        for (int d = 0; d < HDIM; d++) s += qrow[d] * wq[d];
        QD[j] = s;
    }
    __syncthreads();
    float bsum = bc[0] + bq[0] + bcq[0];
#pragma unroll
    for (int r = 0; r < 4; r++) {
        int pi = tid * 4 + r;
        int i = pi >> 5, j = pi & 31;
        const float* crow = CS + i * HDIM;
        const float* qrow = Qg + (size_t)j * HDIM;
        float s = 0.f;
        for (int d = 0; d < HDIM; d++) s += crow[d] * qrow[d] * wcq[d];
        S[pi] = s + CD[i] + QD[j] + bsum;
    }
    __syncthreads();
    int lane = tid & 31, warp = tid >> 5;
    for (int i = warp; i < TT; i += 8) {
        float v = S[i * 32 + lane];
        float mx = v;
        for (int o = 16; o; o >>= 1) mx = fmaxf(mx, __shfl_xor_sync(0xffffffffu, mx, o));
        float e = expf(v - mx);
        float sm = e;
        for (int o = 16; o; o >>= 1) sm += __shfl_xor_sync(0xffffffffu, sm, o);
        Aw[i * 32 + lane] = e / sm;
        if (lane == 0) SMX[i] = mx;
    }
    __syncthreads();
    if (warp == 0) {
        float v = SMX[lane];
        float mx = v;
        for (int o = 16; o; o >>= 1) mx = fmaxf(mx, __shfl_xor_sync(0xffffffffu, mx, o));
        float e = expf(v - mx);
        float sm = e;
        for (int o = 16; o; o >>= 1) sm += __shfl_xor_sync(0xffffffffu, sm, o);
        BV[lane] = e / sm;
    }
    __syncthreads();
    {
        float s = 0.f;
        for (int i = 0; i < TT; i++) s += BV[i] * CS[i * HDIM + tid];
        Q2C[tid] = s;
    }
    __syncthreads();
    float bzv = bz[0];
    for (int i = 0; i < TT; i++) {
        int d = tid;
        float c2q = 0.f;
        for (int j = 0; j < TT; j++) c2q += Aw[i * 32 + j] * Qg[(size_t)j * HDIM + d];
        float cv = CS[i * HDIM + d];
        float term = cv * wz[d] + c2q * wz[HDIM + d] + cv * c2q * wz[2 * HDIM + d]
                   + cv * Q2C[d] * wz[3 * HDIM + d];
        for (int o = 16; o; o >>= 1) term += __shfl_xor_sync(0xffffffffu, term, o);
        if (lane == 0) RED[warp] = term;
        __syncthreads();
        if (tid == 0) {
            float tot = 0.f;
            for (int w2 = 0; w2 < 8; w2++) tot += RED[w2];
            d_p[(pair * MENT + b) * KCAND + i] = tot + bzv;
        }
        __syncthreads();
    }
}

__global__ void zero_kernel(float* __restrict__ out, int n) {
    int idx = blockIdx.x * blockDim.x + threadIdx.x;
    if (idx < n) out[idx] = 0.f;
}

__global__ void score_kernel(const int* __restrict__ cand,
                             const float* __restrict__ wp1, const float* __restrict__ bp1,
                             const float* __restrict__ wp2, const float* __restrict__ bp2,
                             float* __restrict__ out) {
    int b = blockIdx.x, i = threadIdx.x; /* 32 */
    float p1 = d_p[(0 * MENT + b) * KCAND + i];
    float p2 = d_p[(1 * MENT + b) * KCAND + i];
    float sc = wp1[0] * p1 + bp1[0] + wp2[0] * p2 + bp2[0];
    float mx = sc;
    for (int o = 16; o; o >>= 1) mx = fmaxf(mx, __shfl_xor_sync(0xffffffffu, mx, o));
    float e = expf(sc - mx);
    float es = e;
    for (int o = 16; o; o >>= 1) es += __shfl_xor_sync(0xffffffffu, es, o);
    float ssum = sc;
    for (int o = 16; o; o >>= 1) ssum += __shfl_xor_sync(0xffffffffu, ssum, o);
    int col = cand[b * KCAND + i];
    out[(size_t)b * N_ENT + col] = sc;
    out[(size_t)MENT * N_ENT + (size_t)b * N_ENT + col] = e / es;
    out[(size_t)2 * MENT * N_ENT + (size_t)b * N_ENT + col] = sc / ssum;
}

/* ------------------------------- launcher ---------------------------------- */
extern "C" void kernel_launch(void* const* d_in, const int* in_sizes, int n_in,
                              void* d_out, int out_size) {
    const int*   title  = (const int*)d_in[0];
    const int*   body   = (const int*)d_in[1];
    /* d_in[2] mention_vec unused by the reference */
    const int*   ctx    = (const int*)d_in[3];
    const int*   doc    = (const int*)d_in[4];
    const int*   cand   = (const int*)d_in[5];
    const float* emb    = (const float*)d_in[6];
    const float* conv_w = (const float*)d_in[7];
    const float* conv_b = (const float*)d_in[8];
    const float* Wih_f  = (const float*)d_in[9];
    const float* Whh_f  = (const float*)d_in[10];
    const float* bih_f  = (const float*)d_in[11];
    const float* bhh_f  = (const float*)d_in[12];
    const float* Wih_b  = (const float*)d_in[13];
    const float* Whh_b  = (const float*)d_in[14];
    const float* bih_b  = (const float*)d_in[15];
    const float* bhh_b  = (const float*)d_in[16];
    const float* wc  = (const float*)d_in[17];
    const float* bc  = (const float*)d_in[18];
    const float* wq  = (const float*)d_in[19];
    const float* bq  = (const float*)d_in[20];
    const float* wcq = (const float*)d_in[21];
    const float* bcq = (const float*)d_in[22];
    const float* wz  = (const float*)d_in[23];
    const float* bz  = (const float*)d_in[24];
    const float* wp1 = (const float*)d_in[25];
    const float* bp1 = (const float*)d_in[26];
    const float* wp2 = (const float*)d_in[27];
    const float* bp2 = (const float*)d_in[28];
    float* out = (float*)d_out;
    (void)in_sizes; (void)n_in; (void)out_size;

    float *pT, *pB, *pX, *pWTf, *pWTb, *ppF, *ppB;
    cudaGetSymbolAddress((void**)&pT, d_T);
    cudaGetSymbolAddress((void**)&pB, d_Bmat);
    cudaGetSymbolAddress((void**)&pX, d_X);
    cudaGetSymbolAddress((void**)&pWTf, d_WihT_f);
    cudaGetSymbolAddress((void**)&pWTb, d_WihT_b);
    cudaGetSymbolAddress((void**)&ppF, d_preF);
    cudaGetSymbolAddress((void**)&ppB, d_preB);

    /* 1) token table T = emb @ conv_w (reassociated) */
    {
        int n = CCS * EMB * WIN;
        transpose_convw<<<(n + 255) / 256, 256>>>(conv_w);
    }
    sgemm<<<dim3((WIN * CCS + 63) / 64, (VOCAB + 63) / 64), 256>>>(
        emb, pB, pT, VOCAB, WIN * CCS, EMB);

    /* 2) char-CNN features via gather+maxpool */
    conv_kernel<<<N_ENT, CCS>>>(title, LT, 0, conv_b);
    conv_kernel<<<N_ENT, CCS>>>(body, LB, 1, conv_b);
    conv_kernel<<<MENT, CCS>>>(ctx, LC, 2, conv_b);
    conv_kernel<<<1, CCS>>>(doc, LD, 3, conv_b);

    /* 3) gather LSTM input batch X */
    {
        int n = NSEQ * TT * CCS;
        gatherX<<<(n + 255) / 256, 256>>>(cand);
    }

    /* 4) weight transposes */
    {
        int n = G4 * CCS;
        transpose_wih<<<(n + 255) / 256, 256>>>(Wih_f, 0);
        transpose_wih<<<(n + 255) / 256, 256>>>(Wih_b, 1);
    }
    {
        int n = G4 * HH;
        transpose_whh<<<(n + 255) / 256, 256>>>(Whh_f, 0);
        transpose_whh<<<(n + 255) / 256, 256>>>(Whh_b, 1);
    }

    /* 5) input pre-activations for both directions */
    sgemm<<<dim3(G4 / 64, (NSEQ * TT + 63) / 64), 256>>>(pX, pWTf, ppF, NSEQ * TT, G4, CCS);
    sgemm<<<dim3(G4 / 64, (NSEQ * TT + 63) / 64), 256>>>(pX, pWTb, ppB, NSEQ * TT, G4, CCS);

    /* 6) recurrence */
    lstm_kernel<<<dim3((NSEQ + 3) / 4, 2), 512>>>(bih_f, bhh_f, bih_b, bhh_b);

    /* 7) BiDAF attention + projection -> p1/p2 */
    att_kernel<<<dim3(MENT, 2), 256>>>(wc, bc, wq, bq, wcq, bcq, wz, bz);

    /* 8) score, softmax, sum-normalize, scatter */
    {
        int n = 3 * MENT * N_ENT;
        zero_kernel<<<(n + 255) / 256, 256>>>(out, n);
    }
    score_kernel<<<MENT, KCAND>>>(cand, wp1, bp1, wp2, bp2, out);
}

// round 2
// speedup vs baseline: 1.2907x; 1.2907x over previous
#include <cuda_runtime.h>
#include <math.h>
#include <stddef.h>

#define N_ENT 2048
#define MENT  64
#define KCAND 32
#define LT 32
#define LB 128
#define LC 128
#define LD 512
#define VOCAB 5053
#define EMB 300
#define HDIM 256
#define HH 128
#define CCS 512
#define WIN 5
#define NSEQ 193   /* 64 title + 64 body + 64 ctx + 1 doc */
#define TT 32
#define G4 512     /* 4*HH */
#define GCAT 1024  /* fused fwd+bwd gate width */

typedef unsigned long long ull;

/* ------------------------- scratch (device globals) ------------------------ */
__device__ float d_T[(size_t)VOCAB * WIN * CCS];      /* [v][w][c]  51.7MB */
__device__ float d_Bmat[EMB * WIN * CCS];             /* [e][(w,c)] */
__device__ float d_titleF[N_ENT * CCS];
__device__ float d_bodyF[N_ENT * CCS];
__device__ float d_ctxF[MENT * CCS];
__device__ float d_docF[CCS];
__device__ float d_X[NSEQ * TT * CCS];
__device__ float d_WihT[CCS * GCAT];                  /* [k][dir*512+g] */
__device__ float d_pre[NSEQ * TT * GCAT];
__device__ float d_WhhT_f[HH * G4];
__device__ float d_WhhT_b[HH * G4];
__device__ float d_Hcat[NSEQ * TT * HDIM];
__device__ float d_p[2 * MENT * KCAND];

__device__ __forceinline__ float sigm(float x) { return 1.f / (1.f + expf(-x)); }

__device__ __forceinline__ void fma2(ull &d, ull a, ull b) {
    asm("fma.rn.f32x2 %0, %1, %2, %0;" : "+l"(d) : "l"(a), "l"(b));
}
__device__ __forceinline__ ull pack2(float lo, float hi) {
    ull r; asm("mov.b64 %0, {%1, %2};" : "=l"(r) : "f"(lo), "f"(hi)); return r;
}
__device__ __forceinline__ float2 unpack2(ull v) {
    float2 f; asm("mov.b64 {%0, %1}, %2;" : "=f"(f.x), "=f"(f.y) : "l"(v)); return f;
}

/* --------------------------- small transposes ----------------------------- */
__global__ void transpose_convw(const float* __restrict__ conv_w) {
    int idx = blockIdx.x * blockDim.x + threadIdx.x;
    int n = CCS * EMB * WIN;
    if (idx >= n) return;
    int c = idx / (EMB * WIN);
    int rem = idx % (EMB * WIN);
    int e = rem / WIN;
    int w = rem % WIN;
    d_Bmat[e * (WIN * CCS) + w * CCS + c] = conv_w[idx];
}

__global__ void transpose_wih(const float* __restrict__ Wih, int dir) {
    int idx = blockIdx.x * blockDim.x + threadIdx.x;
    int n = G4 * CCS;
    if (idx >= n) return;
    int g = idx / CCS;
    int k = idx % CCS;
    d_WihT[k * GCAT + dir * G4 + g] = Wih[idx];
}

__global__ void transpose_whh(const float* __restrict__ Whh, int sel) {
    int idx = blockIdx.x * blockDim.x + threadIdx.x;
    int n = G4 * HH;
    if (idx >= n) return;
    int g = idx / HH;
    int j = idx % HH;
    float* dst = sel ? d_WhhT_b : d_WhhT_f;
    dst[j * G4 + g] = Whh[idx];
}

/* ------------------------ fp32x2 GEMM (FFMA2) ------------------------------ */
/* C[M,N] = A[M,K] @ B[K,N], row-major. BM=BN=128, BK=16, 256 thr, 8x8/thr.
   Requires N % 128 == 0 (true for both uses: 2560, 1024).                    */
__global__ void __launch_bounds__(256) sgemm2(
        const float* __restrict__ A, const float* __restrict__ B,
        float* __restrict__ C, int M, int N, int K) {
    __shared__ float As[16][132];
    __shared__ float Bs[16][132];
    int tid = threadIdx.x;
    int tx = tid & 15, ty = tid >> 4;
    int m0 = blockIdx.y * 128, n0 = blockIdx.x * 128;
    ull acc[8][4];
#pragma unroll
    for (int i = 0; i < 8; i++)
#pragma unroll
        for (int j = 0; j < 4; j++) acc[i][j] = 0ull;

    for (int k0 = 0; k0 < K; k0 += 16) {
        /* load A tile: 2 float4 per thread, transposed into As[kk][m] */
#pragma unroll
        for (int r = 0; r < 2; r++) {
            int li = tid * 2 + r;          /* 0..511 */
            int row = li >> 2;             /* 0..127 */
            int kq = (li & 3) * 4;         /* 0,4,8,12 */
            float4 v = make_float4(0.f, 0.f, 0.f, 0.f);
            int gm = m0 + row, gk = k0 + kq;
            if (gm < M) {
                if (gk + 3 < K) v = *(const float4*)&A[(size_t)gm * K + gk];
                else {
                    float t0 = (gk + 0 < K) ? A[(size_t)gm * K + gk + 0] : 0.f;
                    float t1 = (gk + 1 < K) ? A[(size_t)gm * K + gk + 1] : 0.f;
                    float t2 = (gk + 2 < K) ? A[(size_t)gm * K + gk + 2] : 0.f;
                    float t3 = (gk + 3 < K) ? A[(size_t)gm * K + gk + 3] : 0.f;
                    v = make_float4(t0, t1, t2, t3);
                }
            }
            As[kq + 0][row] = v.x; As[kq + 1][row] = v.y;
            As[kq + 2][row] = v.z; As[kq + 3][row] = v.w;
        }
        /* load B tile: 2 float4 per thread */
#pragma unroll
        for (int r = 0; r < 2; r++) {
            int li = tid * 2 + r;
            int kk = li >> 5;              /* 0..15 */
            int nq = (li & 31) * 4;        /* 0..124 */
            float4 v = make_float4(0.f, 0.f, 0.f, 0.f);
            int gk = k0 + kk;
            if (gk < K) v = *(const float4*)&B[(size_t)gk * N + n0 + nq];
            *(float4*)&Bs[kk][nq] = v;
        }
        __syncthreads();
#pragma unroll
        for (int kk = 0; kk < 16; kk++) {
            float4 a0 = *(const float4*)&As[kk][ty * 8];
            float4 a1 = *(const float4*)&As[kk][ty * 8 + 4];
            ulonglong2 bA = *(const ulonglong2*)&Bs[kk][tx * 8];
            ulonglong2 bB = *(const ulonglong2*)&Bs[kk][tx * 8 + 4];
            ull bp[4] = {bA.x, bA.y, bB.x, bB.y};
            float ra[8] = {a0.x, a0.y, a0.z, a0.w, a1.x, a1.y, a1.z, a1.w};
            ull ad[8];
#pragma unroll
            for (int i = 0; i < 8; i++) ad[i] = pack2(ra[i], ra[i]);
#pragma unroll
            for (int i = 0; i < 8; i++)
#pragma unroll
                for (int jp = 0; jp < 4; jp++) fma2(acc[i][jp], ad[i], bp[jp]);
        }
        __syncthreads();
    }
#pragma unroll
    for (int i = 0; i < 8; i++) {
        int m = m0 + ty * 8 + i;
        if (m < M) {
#pragma unroll
            for (int jp = 0; jp < 4; jp++) {
                float2 f = unpack2(acc[i][jp]);
                *(float2*)&C[(size_t)m * N + n0 + tx * 8 + 2 * jp] = f;
            }
        }
    }
}

/* -------------------- conv via token table + maxpool ----------------------- */
/* Merged: doc first, then body (longest groups early), ctx, title.
   256 threads, 2 channels each (float2).                                     */
__global__ void __launch_bounds__(256) conv_all(
        const int* __restrict__ title, const int* __restrict__ body,
        const int* __restrict__ ctx, const int* __restrict__ doc,
        const float* __restrict__ bias) {
    int blk = blockIdx.x;
    const int* toks; int L; float* out; int n;
    if (blk == 0)          { toks = doc;   L = LD; out = d_docF;   n = 0; }
    else if (blk <= 2048)  { toks = body;  L = LB; out = d_bodyF;  n = blk - 1; }
    else if (blk <= 2112)  { toks = ctx;   L = LC; out = d_ctxF;   n = blk - 2049; }
    else                   { toks = title; L = LT; out = d_titleF; n = blk - 2113; }
    int c2 = threadIdx.x;                /* channel pair index, 0..255 */
    __shared__ int st[LD];
    for (int i = c2; i < L; i += 256) st[i] = toks[(size_t)n * L + i];
    __syncthreads();
    float2 b = *(const float2*)&bias[2 * c2];
    float2 m = make_float2(0.f, 0.f);
    int P = L - WIN + 1;
    for (int p = 0; p < P; p++) {
        float2 acc = b;
#pragma unroll
        for (int w = 0; w < WIN; w++) {
            int v = st[p + w];
            float2 tv = *(const float2*)&d_T[((size_t)v * WIN + w) * CCS + 2 * c2];
            acc.x += tv.x; acc.y += tv.y;
        }
        m.x = fmaxf(m.x, acc.x);
        m.y = fmaxf(m.y, acc.y);
    }
    *(float2*)&out[(size_t)n * CCS + 2 * c2] = m;
}

/* -------------------------- gather LSTM inputs ----------------------------- */
__global__ void gatherX(const int* __restrict__ cand) {
    int idx = blockIdx.x * blockDim.x + threadIdx.x;
    int n = NSEQ * TT * CCS;
    if (idx >= n) return;
    int seq = idx / (TT * CCS);
    int r = idx % (TT * CCS);
    int t = r / CCS;
    int c = r % CCS;
    float v;
    if (seq < 64)       v = d_titleF[(size_t)cand[seq * TT + t] * CCS + c];
    else if (seq < 128) v = d_bodyF[(size_t)cand[(seq - 64) * TT + t] * CCS + c];
    else if (seq < 192) v = d_ctxF[(seq - 128) * CCS + c];
    else                v = d_docF[c];
    d_X[idx] = v;
}

/* ----------------------------- LSTM recurrence ----------------------------- */
/* grid (ceil(193/4), 2), 512 threads. 4 sequences/block/direction.
   h kept transposed [HH][4] so one LDS.128 serves all 4 seqs; FFMA2 pairs
   accumulate (s0,s1) and (s2,s3) together.                                   */
__global__ void __launch_bounds__(512) lstm_kernel(
        const float* __restrict__ bih_f, const float* __restrict__ bhh_f,
        const float* __restrict__ bih_b, const float* __restrict__ bhh_b) {
    int dir = blockIdx.y;
    int s0 = blockIdx.x * 4;
    const float* pre = d_pre + dir * G4;
    const float* WT  = dir ? d_WhhT_b : d_WhhT_f;
    int g = threadIdx.x;  /* 0..511 */
    float bias = dir ? (bih_b[g] + bhh_b[g]) : (bih_f[g] + bhh_f[g]);
    __shared__ float shT[HH][4];      /* h transposed: [j][s] */
    __shared__ float sg[4][G4];
    int so = g >> 7, d = g & 127;     /* owner mapping */
    float creg = 0.f;
    if (g < 512) shT[d][so] = 0.f;    /* covers all HH*4 via (d,so) bijection */
    __syncthreads();
    int nv = NSEQ - s0; if (nv > 4) nv = 4;
    int sc0 = s0, sc1 = min(s0 + 1, NSEQ - 1), sc2 = min(s0 + 2, NSEQ - 1), sc3 = min(s0 + 3, NSEQ - 1);
    for (int step = 0; step < TT; step++) {
        int t = dir ? (TT - 1 - step) : step;
        float p0 = pre[((size_t)sc0 * TT + t) * GCAT + g] + bias;
        float p1 = pre[((size_t)sc1 * TT + t) * GCAT + g] + bias;
        float p2 = pre[((size_t)sc2 * TT + t) * GCAT + g] + bias;
        float p3 = pre[((size_t)sc3 * TT + t) * GCAT + g] + bias;
        ull a01 = pack2(p0, p1);
        ull a23 = pack2(p2, p3);
        const float* wcol = WT + g;
#pragma unroll 8
        for (int j = 0; j < HH; j++) {
            float wv = __ldg(wcol + j * G4);
            ulonglong2 h2 = *(const ulonglong2*)&shT[j][0];
            ull wd = pack2(wv, wv);
            fma2(a01, wd, h2.x);
            fma2(a23, wd, h2.y);
        }
        float2 f01 = unpack2(a01);
        float2 f23 = unpack2(a23);
        sg[0][g] = f01.x; sg[1][g] = f01.y; sg[2][g] = f23.x; sg[3][g] = f23.y;
        __syncthreads();
        if (so < nv) {
            float iv = sg[so][d];
            float fv = sg[so][d + HH];
            float gv = sg[so][d + 2 * HH];
            float ov = sg[so][d + 3 * HH];
            float cn = sigm(fv) * creg + sigm(iv) * tanhf(gv);
            float hn = sigm(ov) * tanhf(cn);
            creg = cn;
            shT[d][so] = hn;
            d_Hcat[((size_t)(s0 + so) * TT + t) * HDIM + dir * HH + d] = hn;
        }
        __syncthreads();
    }
}

/* ------------------------------ BiDAF + score ------------------------------ */
__global__ void att_kernel(const float* __restrict__ wc, const float* __restrict__ bc,
                           const float* __restrict__ wq, const float* __restrict__ bq,
                           const float* __restrict__ wcq, const float* __restrict__ bcq,
                           const float* __restrict__ wz, const float* __restrict__ bz) {
    int b = blockIdx.x;
    int pair = blockIdx.y;
    int tid = threadIdx.x;
    int cseq = pair ? 192 : 128 + b;
    int qseq = pair ? 64 + b : b;
    const float* Cg = d_Hcat + (size_t)cseq * TT * HDIM;
    const float* Qg = d_Hcat + (size_t)qseq * TT * HDIM;
    __shared__ float CS[TT * HDIM];
    __shared__ float S[TT * TT];
    __shared__ float Aw[TT * TT];
    __shared__ float CD[TT], QD[TT], SMX[TT], BV[TT];
    __shared__ float Q2C[HDIM];
    __shared__ float RED[8];
    for (int i = tid; i < TT * HDIM; i += 256) CS[i] = Cg[i];
    __syncthreads();
    if (tid < TT) {
        float s = 0.f;
        const float* crow = CS + tid * HDIM;
        for (int d = 0; d < HDIM; d++) s += crow[d] * wc[d];
        CD[tid] = s;
    } else if (tid < 2 * TT) {
        int j = tid - TT;
        float s = 0.f;
        const float* qrow = Qg + (size_t)j * HDIM;
        for (int d = 0; d < HDIM; d++) s += qrow[d] * wq[d];
        QD[j] = s;
    }
    __syncthreads();
    float bsum = bc[0] + bq[0] + bcq[0];
#pragma unroll
    for (int r = 0; r < 4; r++) {
        int pi = tid * 4 + r;
        int i = pi >> 5, j = pi & 31;
        const float* crow = CS + i * HDIM;
        const float* qrow = Qg + (size_t)j * HDIM;
        float s = 0.f;
        for (int d = 0; d < HDIM; d++) s += crow[d] * qrow[d] * wcq[d];
        S[pi] = s + CD[i] + QD[j] + bsum;
    }
    __syncthreads();
    int lane = tid & 31, warp = tid >> 5;
    for (int i = warp; i < TT; i += 8) {
        float v = S[i * 32 + lane];
        float mx = v;
        for (int o = 16; o; o >>= 1) mx = fmaxf(mx, __shfl_xor_sync(0xffffffffu, mx, o));
        float e = expf(v - mx);
        float sm = e;
        for (int o = 16; o; o >>= 1) sm += __shfl_xor_sync(0xffffffffu, sm, o);
        Aw[i * 32 + lane] = e / sm;
        if (lane == 0) SMX[i] = mx;
    }
    __syncthreads();
    if (warp == 0) {
        float v = SMX[lane];
        float mx = v;
        for (int o = 16; o; o >>= 1) mx = fmaxf(mx, __shfl_xor_sync(0xffffffffu, mx, o));
        float e = expf(v - mx);
        float sm = e;
        for (int o = 16; o; o >>= 1) sm += __shfl_xor_sync(0xffffffffu, sm, o);
        BV[lane] = e / sm;
    }
    __syncthreads();
    {
        float s = 0.f;
        for (int i = 0; i < TT; i++) s += BV[i] * CS[i * HDIM + tid];
        Q2C[tid] = s;
    }
    __syncthreads();
    float bzv = bz[0];
    for (int i = 0; i < TT; i++) {
        int d = tid;
        float c2q = 0.f;
        for (int j = 0; j < TT; j++) c2q += Aw[i * 32 + j] * Qg[(size_t)j * HDIM + d];
        float cv = CS[i * HDIM + d];
        float term = cv * wz[d] + c2q * wz[HDIM + d] + cv * c2q * wz[2 * HDIM + d]
                   + cv * Q2C[d] * wz[3 * HDIM + d];
        for (int o = 16; o; o >>= 1) term += __shfl_xor_sync(0xffffffffu, term, o);
        if (lane == 0) RED[warp] = term;
        __syncthreads();
        if (tid == 0) {
            float tot = 0.f;
            for (int w2 = 0; w2 < 8; w2++) tot += RED[w2];
            d_p[(pair * MENT + b) * KCAND + i] = tot + bzv;
        }
        __syncthreads();
    }
}

__global__ void zero_kernel(float* __restrict__ out, int n) {
    int idx = blockIdx.x * blockDim.x + threadIdx.x;
    if (idx < n) out[idx] = 0.f;
}

__global__ void score_kernel(const int* __restrict__ cand,
                             const float* __restrict__ wp1, const float* __restrict__ bp1,
                             const float* __restrict__ wp2, const float* __restrict__ bp2,
                             float* __restrict__ out) {
    int b = blockIdx.x, i = threadIdx.x; /* 32 */
    float p1 = d_p[(0 * MENT + b) * KCAND + i];
    float p2 = d_p[(1 * MENT + b) * KCAND + i];
    float sc = wp1[0] * p1 + bp1[0] + wp2[0] * p2 + bp2[0];
    float mx = sc;
    for (int o = 16; o; o >>= 1) mx = fmaxf(mx, __shfl_xor_sync(0xffffffffu, mx, o));
    float e = expf(sc - mx);
    float es = e;
    for (int o = 16; o; o >>= 1) es += __shfl_xor_sync(0xffffffffu, es, o);
    float ssum = sc;
    for (int o = 16; o; o >>= 1) ssum += __shfl_xor_sync(0xffffffffu, ssum, o);
    int col = cand[b * KCAND + i];
    out[(size_t)b * N_ENT + col] = sc;
    out[(size_t)MENT * N_ENT + (size_t)b * N_ENT + col] = e / es;
    out[(size_t)2 * MENT * N_ENT + (size_t)b * N_ENT + col] = sc / ssum;
}

/* ------------------------------- launcher ---------------------------------- */
extern "C" void kernel_launch(void* const* d_in, const int* in_sizes, int n_in,
                              void* d_out, int out_size) {
    const int*   title  = (const int*)d_in[0];
    const int*   body   = (const int*)d_in[1];
    const int*   ctx    = (const int*)d_in[3];
    const int*   doc    = (const int*)d_in[4];
    const int*   cand   = (const int*)d_in[5];
    const float* emb    = (const float*)d_in[6];
    const float* conv_w = (const float*)d_in[7];
    const float* conv_b = (const float*)d_in[8];
    const float* Wih_f  = (const float*)d_in[9];
    const float* Whh_f  = (const float*)d_in[10];
    const float* bih_f  = (const float*)d_in[11];
    const float* bhh_f  = (const float*)d_in[12];
    const float* Wih_b  = (const float*)d_in[13];
    const float* Whh_b  = (const float*)d_in[14];
    const float* bih_b  = (const float*)d_in[15];
    const float* bhh_b  = (const float*)d_in[16];
    const float* wc  = (const float*)d_in[17];
    const float* bc  = (const float*)d_in[18];
    const float* wq  = (const float*)d_in[19];
    const float* bq  = (const float*)d_in[20];
    const float* wcq = (const float*)d_in[21];
    const float* bcq = (const float*)d_in[22];
    const float* wz  = (const float*)d_in[23];
    const float* bz  = (const float*)d_in[24];
    const float* wp1 = (const float*)d_in[25];
    const float* bp1 = (const float*)d_in[26];
    const float* wp2 = (const float*)d_in[27];
    const float* bp2 = (const float*)d_in[28];
    float* out = (float*)d_out;
    (void)in_sizes; (void)n_in; (void)out_size;

    float *pT, *pB, *pX, *pWT, *pPre;
    cudaGetSymbolAddress((void**)&pT, d_T);
    cudaGetSymbolAddress((void**)&pB, d_Bmat);
    cudaGetSymbolAddress((void**)&pX, d_X);
    cudaGetSymbolAddress((void**)&pWT, d_WihT);
    cudaGetSymbolAddress((void**)&pPre, d_pre);

    /* weight transposes (independent, cheap) */
    {
        int n = CCS * EMB * WIN;
        transpose_convw<<<(n + 255) / 256, 256>>>(conv_w);
    }
    {
        int n = G4 * CCS;
        transpose_wih<<<(n + 255) / 256, 256>>>(Wih_f, 0);
        transpose_wih<<<(n + 255) / 256, 256>>>(Wih_b, 1);
    }
    {
        int n = G4 * HH;
        transpose_whh<<<(n + 255) / 256, 256>>>(Whh_f, 0);
        transpose_whh<<<(n + 255) / 256, 256>>>(Whh_b, 1);
    }

    /* 1) token table T = emb @ Bmat : [5053 x 2560], K=300 */
    sgemm2<<<dim3((WIN * CCS) / 128, (VOCAB + 127) / 128), 256>>>(
        emb, pB, pT, VOCAB, WIN * CCS, EMB);

    /* 2) char-CNN features (merged, doc+body first) */
    conv_all<<<1 + N_ENT + MENT + N_ENT, 256>>>(title, body, ctx, doc, conv_b);

    /* 3) gather LSTM input batch X */
    {
        int n = NSEQ * TT * CCS;
        gatherX<<<(n + 255) / 256, 256>>>(cand);
    }

    /* 4) fused input pre-activations, both directions: [6176 x 1024], K=512 */
    sgemm2<<<dim3(GCAT / 128, (NSEQ * TT + 127) / 128), 256>>>(
        pX, pWT, pPre, NSEQ * TT, GCAT, CCS);

    /* 5) recurrence */
    lstm_kernel<<<dim3((NSEQ + 3) / 4, 2), 512>>>(bih_f, bhh_f, bih_b, bhh_b);

    /* 6) BiDAF attention + projection -> p1/p2 */
    att_kernel<<<dim3(MENT, 2), 256>>>(wc, bc, wq, bq, wcq, bcq, wz, bz);

    /* 7) score, softmax, sum-normalize, scatter */
    {
        int n = 3 * MENT * N_ENT;
        zero_kernel<<<(n + 255) / 256, 256>>>(out, n);
    }
    score_kernel<<<MENT, KCAND>>>(cand, wp1, bp1, wp2, bp2, out);
}

// round 3
// speedup vs baseline: 1.4152x; 1.0965x over previous
#include <cuda_runtime.h>
#include <math.h>
#include <stddef.h>

#define N_ENT 2048
#define MENT  64
#define KCAND 32
#define LT 32
#define LB 128
#define LC 128
#define LD 512
#define VOCAB 5053
#define EMB 300
#define HDIM 256
#define HH 128
#define CCS 512
#define WIN 5
#define NSEQ 193   /* 64 title + 64 body + 64 ctx + 1 doc */
#define TT 32
#define G4 512     /* 4*HH */
#define GCAT 1024  /* fused fwd+bwd gate width */
#define NFEAT 4161 /* 2048 title + 2048 body + 64 ctx + 1 doc */

typedef unsigned long long ull;

/* ------------------------- scratch (device globals) ------------------------ */
__device__ float d_T[(size_t)VOCAB * WIN * CCS];      /* [v][w][c]  51.7MB */
__device__ float d_Bmat[EMB * WIN * CCS];             /* [e][(w,c)] */
__device__ float d_F[NFEAT * CCS];                    /* all char-CNN features */
__device__ float d_WihT[CCS * GCAT];                  /* [k][dir*512+g] */
__device__ float d_preAll[(size_t)NFEAT * GCAT];
__device__ int   d_rowIdx[NSEQ * TT];
__device__ float d_WhhT_f[HH * G4];
__device__ float d_WhhT_b[HH * G4];
__device__ float d_Hcat[NSEQ * TT * HDIM];
__device__ float d_p[2 * MENT * KCAND];

__device__ __forceinline__ float sigm(float x) { return 1.f / (1.f + expf(-x)); }

__device__ __forceinline__ void fma2(ull &d, ull a, ull b) {
    asm("fma.rn.f32x2 %0, %1, %2, %0;" : "+l"(d) : "l"(a), "l"(b));
}
__device__ __forceinline__ ull pack2(float lo, float hi) {
    ull r; asm("mov.b64 %0, {%1, %2};" : "=l"(r) : "f"(lo), "f"(hi)); return r;
}
__device__ __forceinline__ float2 unpack2(ull v) {
    float2 f; asm("mov.b64 {%0, %1}, %2;" : "=f"(f.x), "=f"(f.y) : "l"(v)); return f;
}

/* --------------------------- small transposes ----------------------------- */
__global__ void transpose_convw(const float* __restrict__ conv_w) {
    int idx = blockIdx.x * blockDim.x + threadIdx.x;
    int n = CCS * EMB * WIN;
    if (idx >= n) return;
    int c = idx / (EMB * WIN);
    int rem = idx % (EMB * WIN);
    int e = rem / WIN;
    int w = rem % WIN;
    d_Bmat[e * (WIN * CCS) + w * CCS + c] = conv_w[idx];
}

__global__ void transpose_wih(const float* __restrict__ Wih, int dir) {
    int idx = blockIdx.x * blockDim.x + threadIdx.x;
    int n = G4 * CCS;
    if (idx >= n) return;
    int g = idx / CCS;
    int k = idx % CCS;
    d_WihT[k * GCAT + dir * G4 + g] = Wih[idx];
}

__global__ void transpose_whh(const float* __restrict__ Whh, int sel) {
    int idx = blockIdx.x * blockDim.x + threadIdx.x;
    int n = G4 * HH;
    if (idx >= n) return;
    int g = idx / HH;
    int j = idx % HH;
    float* dst = sel ? d_WhhT_b : d_WhhT_f;
    dst[j * G4 + g] = Whh[idx];
}

/* ----------------- fp32x2 GEMM (FFMA2), double-buffered -------------------- */
/* C[M,N] = A[M,K] @ B[K,N], row-major. BM=BN=128, BK=16, 256 thr, 8x8/thr.
   Requires N % 128 == 0.                                                     */
__global__ void __launch_bounds__(256) sgemm2(
        const float* __restrict__ A, const float* __restrict__ B,
        float* __restrict__ C, int M, int N, int K) {
    __shared__ float As[2][16][132];
    __shared__ float Bs[2][16][132];
    int tid = threadIdx.x;
    int tx = tid & 15, ty = tid >> 4;
    int m0 = blockIdx.y * 128, n0 = blockIdx.x * 128;
    ull acc[8][4];
#pragma unroll
    for (int i = 0; i < 8; i++)
#pragma unroll
        for (int j = 0; j < 4; j++) acc[i][j] = 0ull;

    int nk = (K + 15) / 16;

    /* per-thread load coordinates */
    int aRow0 = (tid * 2) >> 2;            /* 0..127 */
    int aK0 = ((tid * 2) & 3) * 4;
    int aRow1 = (tid * 2 + 1) >> 2;
    int aK1 = ((tid * 2 + 1) & 3) * 4;
    int bK0 = (tid * 2) >> 5;              /* 0..15 */
    int bN0 = ((tid * 2) & 31) * 4;
    int bK1 = (tid * 2 + 1) >> 5;
    int bN1 = ((tid * 2 + 1) & 31) * 4;

    float4 ra0, ra1, rb0, rb1;

    /* fetch tile 0 */
    {
        int k0 = 0;
        ra0 = make_float4(0.f, 0.f, 0.f, 0.f);
        ra1 = make_float4(0.f, 0.f, 0.f, 0.f);
        rb0 = make_float4(0.f, 0.f, 0.f, 0.f);
        rb1 = make_float4(0.f, 0.f, 0.f, 0.f);
        if (m0 + aRow0 < M && k0 + aK0 + 3 < K)
            ra0 = *(const float4*)&A[(size_t)(m0 + aRow0) * K + k0 + aK0];
        else if (m0 + aRow0 < M) {
            float* p = (float*)&ra0;
            for (int q = 0; q < 4; q++) if (k0 + aK0 + q < K) p[q] = A[(size_t)(m0 + aRow0) * K + k0 + aK0 + q];
        }
        if (m0 + aRow1 < M && k0 + aK1 + 3 < K)
            ra1 = *(const float4*)&A[(size_t)(m0 + aRow1) * K + k0 + aK1];
        else if (m0 + aRow1 < M) {
            float* p = (float*)&ra1;
            for (int q = 0; q < 4; q++) if (k0 + aK1 + q < K) p[q] = A[(size_t)(m0 + aRow1) * K + k0 + aK1 + q];
        }
        if (k0 + bK0 < K) rb0 = *(const float4*)&B[(size_t)(k0 + bK0) * N + n0 + bN0];
        if (k0 + bK1 < K) rb1 = *(const float4*)&B[(size_t)(k0 + bK1) * N + n0 + bN1];
    }
    /* store tile 0 */
    As[0][aK0 + 0][aRow0] = ra0.x; As[0][aK0 + 1][aRow0] = ra0.y;
    As[0][aK0 + 2][aRow0] = ra0.z; As[0][aK0 + 3][aRow0] = ra0.w;
    As[0][aK1 + 0][aRow1] = ra1.x; As[0][aK1 + 1][aRow1] = ra1.y;
    As[0][aK1 + 2][aRow1] = ra1.z; As[0][aK1 + 3][aRow1] = ra1.w;
    *(float4*)&Bs[0][bK0][bN0] = rb0;
    *(float4*)&Bs[0][bK1][bN1] = rb1;
    __syncthreads();

    for (int it = 0; it < nk; it++) {
        int cur = it & 1;
        if (it + 1 < nk) {
            int k0 = (it + 1) * 16;
            ra0 = make_float4(0.f, 0.f, 0.f, 0.f);
            ra1 = make_float4(0.f, 0.f, 0.f, 0.f);
            rb0 = make_float4(0.f, 0.f, 0.f, 0.f);
            rb1 = make_float4(0.f, 0.f, 0.f, 0.f);
            if (m0 + aRow0 < M && k0 + aK0 + 3 < K)
                ra0 = *(const float4*)&A[(size_t)(m0 + aRow0) * K + k0 + aK0];
            else if (m0 + aRow0 < M) {
                float* p = (float*)&ra0;
                for (int q = 0; q < 4; q++) if (k0 + aK0 + q < K) p[q] = A[(size_t)(m0 + aRow0) * K + k0 + aK0 + q];
            }
            if (m0 + aRow1 < M && k0 + aK1 + 3 < K)
                ra1 = *(const float4*)&A[(size_t)(m0 + aRow1) * K + k0 + aK1];
            else if (m0 + aRow1 < M) {
                float* p = (float*)&ra1;
                for (int q = 0; q < 4; q++) if (k0 + aK1 + q < K) p[q] = A[(size_t)(m0 + aRow1) * K + k0 + aK1 + q];
            }
            if (k0 + bK0 < K) rb0 = *(const float4*)&B[(size_t)(k0 + bK0) * N + n0 + bN0];
            if (k0 + bK1 < K) rb1 = *(const float4*)&B[(size_t)(k0 + bK1) * N + n0 + bN1];
        }
#pragma unroll
        for (int kk = 0; kk < 16; kk++) {
            float4 a0 = *(const float4*)&As[cur][kk][ty * 8];
            float4 a1 = *(const float4*)&As[cur][kk][ty * 8 + 4];
            ulonglong2 bA = *(const ulonglong2*)&Bs[cur][kk][tx * 8];
            ulonglong2 bB = *(const ulonglong2*)&Bs[cur][kk][tx * 8 + 4];
            ull bp[4] = {bA.x, bA.y, bB.x, bB.y};
            float rav[8] = {a0.x, a0.y, a0.z, a0.w, a1.x, a1.y, a1.z, a1.w};
            ull ad[8];
#pragma unroll
            for (int i = 0; i < 8; i++) ad[i] = pack2(rav[i], rav[i]);
#pragma unroll
            for (int i = 0; i < 8; i++)
#pragma unroll
                for (int jp = 0; jp < 4; jp++) fma2(acc[i][jp], ad[i], bp[jp]);
        }
        if (it + 1 < nk) {
            int nxt = cur ^ 1;
            As[nxt][aK0 + 0][aRow0] = ra0.x; As[nxt][aK0 + 1][aRow0] = ra0.y;
            As[nxt][aK0 + 2][aRow0] = ra0.z; As[nxt][aK0 + 3][aRow0] = ra0.w;
            As[nxt][aK1 + 0][aRow1] = ra1.x; As[nxt][aK1 + 1][aRow1] = ra1.y;
            As[nxt][aK1 + 2][aRow1] = ra1.z; As[nxt][aK1 + 3][aRow1] = ra1.w;
            *(float4*)&Bs[nxt][bK0][bN0] = rb0;
            *(float4*)&Bs[nxt][bK1][bN1] = rb1;
            __syncthreads();
        }
    }
#pragma unroll
    for (int i = 0; i < 8; i++) {
        int m = m0 + ty * 8 + i;
        if (m < M) {
#pragma unroll
            for (int jp = 0; jp < 4; jp++) {
                float2 f = unpack2(acc[i][jp]);
                *(float2*)&C[(size_t)m * N + n0 + tx * 8 + 2 * jp] = f;
            }
        }
    }
}

/* -------------------- conv via token table + maxpool ----------------------- */
/* All features go to d_F: rows 0..2047 title, 2048..4095 body, 4096..4159 ctx,
   4160 doc. Longest sequences scheduled first (doc, body).                   */
__global__ void __launch_bounds__(256) conv_all(
        const int* __restrict__ title, const int* __restrict__ body,
        const int* __restrict__ ctx, const int* __restrict__ doc,
        const float* __restrict__ bias) {
    int blk = blockIdx.x;
    const int* toks; int L; int row;
    if (blk == 0)          { toks = doc;   L = LD; row = 4160; }
    else if (blk <= 2048)  { toks = body + (size_t)(blk - 1) * LB;    L = LB; row = 2048 + blk - 1; }
    else if (blk <= 2112)  { toks = ctx + (size_t)(blk - 2049) * LC;  L = LC; row = 4096 + blk - 2049; }
    else                   { toks = title + (size_t)(blk - 2113) * LT; L = LT; row = blk - 2113; }
    int c2 = threadIdx.x;                /* channel pair index, 0..255 */
    __shared__ int st[LD];
    for (int i = c2; i < L; i += 256) st[i] = toks[i];
    __syncthreads();
    float2 b = *(const float2*)&bias[2 * c2];
    float2 m = make_float2(0.f, 0.f);
    int P = L - WIN + 1;
    for (int p = 0; p < P; p++) {
        float2 acc = b;
#pragma unroll
        for (int w = 0; w < WIN; w++) {
            int v = st[p + w];
            float2 tv = *(const float2*)&d_T[((size_t)v * WIN + w) * CCS + 2 * c2];
            acc.x += tv.x; acc.y += tv.y;
        }
        m.x = fmaxf(m.x, acc.x);
        m.y = fmaxf(m.y, acc.y);
    }
    *(float2*)&d_F[(size_t)row * CCS + 2 * c2] = m;
}

/* -------------------------- LSTM row index table --------------------------- */
__global__ void build_rowidx(const int* __restrict__ cand) {
    int idx = blockIdx.x * blockDim.x + threadIdx.x;
    if (idx >= NSEQ * TT) return;
    int seq = idx / TT, t = idx % TT;
    int r;
    if (seq < 64)       r = cand[seq * TT + t];
    else if (seq < 128) r = 2048 + cand[(seq - 64) * TT + t];
    else if (seq < 192) r = 4096 + (seq - 128);
    else                r = 4160;
    d_rowIdx[idx] = r;
}

/* ----------------------------- LSTM recurrence ----------------------------- */
/* grid (ceil(193/4), 2), 512 threads. 4 sequences/block/direction. Gathers
   pre-activation rows from d_preAll via d_rowIdx.                            */
__global__ void __launch_bounds__(512) lstm_kernel(
        const float* __restrict__ bih_f, const float* __restrict__ bhh_f,
        const float* __restrict__ bih_b, const float* __restrict__ bhh_b) {
    int dir = blockIdx.y;
    int s0 = blockIdx.x * 4;
    const float* WT = dir ? d_WhhT_b : d_WhhT_f;
    int g = threadIdx.x;  /* 0..511 */
    float bias = dir ? (bih_b[g] + bhh_b[g]) : (bih_f[g] + bhh_f[g]);
    __shared__ float shT[HH][4];      /* h transposed: [j][s] */
    __shared__ float sg[4][G4];
    __shared__ int ridx[4][TT];
    int so = g >> 7, d = g & 127;
    float creg = 0.f;
    shT[d][so] = 0.f;
    for (int i = g; i < 4 * TT; i += 512) {
        int s = i >> 5, t = i & 31;
        int seq = s0 + s; if (seq >= NSEQ) seq = NSEQ - 1;
        ridx[s][t] = d_rowIdx[seq * TT + t];
    }
    __syncthreads();
    int nv = NSEQ - s0; if (nv > 4) nv = 4;
    const float* preBase = d_preAll + dir * G4 + g;
    for (int step = 0; step < TT; step++) {
        int t = dir ? (TT - 1 - step) : step;
        float p0 = preBase[(size_t)ridx[0][t] * GCAT] + bias;
        float p1 = preBase[(size_t)ridx[1][t] * GCAT] + bias;
        float p2 = preBase[(size_t)ridx[2][t] * GCAT] + bias;
        float p3 = preBase[(size_t)ridx[3][t] * GCAT] + bias;
        ull a01 = pack2(p0, p1);
        ull a23 = pack2(p2, p3);
        const float* wcol = WT + g;
#pragma unroll 8
        for (int j = 0; j < HH; j++) {
            float wv = __ldg(wcol + j * G4);
            ulonglong2 h2 = *(const ulonglong2*)&shT[j][0];
            ull wd = pack2(wv, wv);
            fma2(a01, wd, h2.x);
            fma2(a23, wd, h2.y);
        }
        float2 f01 = unpack2(a01);
        float2 f23 = unpack2(a23);
        sg[0][g] = f01.x; sg[1][g] = f01.y; sg[2][g] = f23.x; sg[3][g] = f23.y;
        __syncthreads();
        if (so < nv) {
            float iv = sg[so][d];
            float fv = sg[so][d + HH];
            float gv = sg[so][d + 2 * HH];
            float ov = sg[so][d + 3 * HH];
            float cn = sigm(fv) * creg + sigm(iv) * tanhf(gv);
            float hn = sigm(ov) * tanhf(cn);
            creg = cn;
            shT[d][so] = hn;
            d_Hcat[((size_t)(s0 + so) * TT + t) * HDIM + dir * HH + d] = hn;
        }
        __syncthreads();
    }
}

/* ------------------------------ BiDAF + score ------------------------------ */
__global__ void att_kernel(const float* __restrict__ wc, const float* __restrict__ bc,
                           const float* __restrict__ wq, const float* __restrict__ bq,
                           const float* __restrict__ wcq, const float* __restrict__ bcq,
                           const float* __restrict__ wz, const float* __restrict__ bz) {
    int b = blockIdx.x;
    int pair = blockIdx.y;
    int tid = threadIdx.x;
    int cseq = pair ? 192 : 128 + b;
    int qseq = pair ? 64 + b : b;
    const float* Cg = d_Hcat + (size_t)cseq * TT * HDIM;
    const float* Qg = d_Hcat + (size_t)qseq * TT * HDIM;
    __shared__ float CS[TT * HDIM];
    __shared__ float S[TT * TT];
    __shared__ float Aw[TT * TT];
    __shared__ float CD[TT], QD[TT], SMX[TT], BV[TT];
    __shared__ float Q2C[HDIM];
    __shared__ float RED[8];
    for (int i = tid; i < TT * HDIM; i += 256) CS[i] = Cg[i];
    __syncthreads();
    if (tid < TT) {
        float s = 0.f;
        const float* crow = CS + tid * HDIM;
        for (int d = 0; d < HDIM; d++) s += crow[d] * wc[d];
        CD[tid] = s;
    } else if (tid < 2 * TT) {
        int j = tid - TT;
        float s = 0.f;
        const float* qrow = Qg + (size_t)j * HDIM;
        for (int d = 0; d < HDIM; d++) s += qrow[d] * wq[d];
        QD[j] = s;
    }
    __syncthreads();
    float bsum = bc[0] + bq[0] + bcq[0];
#pragma unroll
    for (int r = 0; r < 4; r++) {
        int pi = tid * 4 + r;
        int i = pi >> 5, j = pi & 31;
        const float* crow = CS + i * HDIM;
        const float* qrow = Qg + (size_t)j * HDIM;
        float s = 0.f;
        for (int d = 0; d < HDIM; d++) s += crow[d] * qrow[d] * wcq[d];
        S[pi] = s + CD[i] + QD[j] + bsum;
    }
    __syncthreads();
    int lane = tid & 31, warp = tid >> 5;
    for (int i = warp; i < TT; i += 8) {
        float v = S[i * 32 + lane];
        float mx = v;
        for (int o = 16; o; o >>= 1) mx = fmaxf(mx, __shfl_xor_sync(0xffffffffu, mx, o));
        float e = expf(v - mx);
        float sm = e;
        for (int o = 16; o; o >>= 1) sm += __shfl_xor_sync(0xffffffffu, sm, o);
        Aw[i * 32 + lane] = e / sm;
        if (lane == 0) SMX[i] = mx;
    }
    __syncthreads();
    if (warp == 0) {
        float v = SMX[lane];
        float mx = v;
        for (int o = 16; o; o >>= 1) mx = fmaxf(mx, __shfl_xor_sync(0xffffffffu, mx, o));
        float e = expf(v - mx);
        float sm = e;
        for (int o = 16; o; o >>= 1) sm += __shfl_xor_sync(0xffffffffu, sm, o);
        BV[lane] = e / sm;
    }
    __syncthreads();
    {
        float s = 0.f;
        for (int i = 0; i < TT; i++) s += BV[i] * CS[i * HDIM + tid];
        Q2C[tid] = s;
    }
    __syncthreads();
    float bzv = bz[0];
    for (int i = 0; i < TT; i++) {
        int d = tid;
        float c2q = 0.f;
        for (int j = 0; j < TT; j++) c2q += Aw[i * 32 + j] * Qg[(size_t)j * HDIM + d];
        float cv = CS[i * HDIM + d];
        float term = cv * wz[d] + c2q * wz[HDIM + d] + cv * c2q * wz[2 * HDIM + d]
                   + cv * Q2C[d] * wz[3 * HDIM + d];
        for (int o = 16; o; o >>= 1) term += __shfl_xor_sync(0xffffffffu, term, o);
        if (lane == 0) RED[warp] = term;
        __syncthreads();
        if (tid == 0) {
            float tot = 0.f;
            for (int w2 = 0; w2 < 8; w2++) tot += RED[w2];
            d_p[(pair * MENT + b) * KCAND + i] = tot + bzv;
        }
        __syncthreads();
    }
}

__global__ void zero_kernel(float* __restrict__ out, int n) {
    int idx = blockIdx.x * blockDim.x + threadIdx.x;
    if (idx < n) out[idx] = 0.f;
}

__global__ void score_kernel(const int* __restrict__ cand,
                             const float* __restrict__ wp1, const float* __restrict__ bp1,
                             const float* __restrict__ wp2, const float* __restrict__ bp2,
                             float* __restrict__ out) {
    int b = blockIdx.x, i = threadIdx.x; /* 32 */
    float p1 = d_p[(0 * MENT + b) * KCAND + i];
    float p2 = d_p[(1 * MENT + b) * KCAND + i];
    float sc = wp1[0] * p1 + bp1[0] + wp2[0] * p2 + bp2[0];
    float mx = sc;
    for (int o = 16; o; o >>= 1) mx = fmaxf(mx, __shfl_xor_sync(0xffffffffu, mx, o));
    float e = expf(sc - mx);
    float es = e;
    for (int o = 16; o; o >>= 1) es += __shfl_xor_sync(0xffffffffu, es, o);
    float ssum = sc;
    for (int o = 16; o; o >>= 1) ssum += __shfl_xor_sync(0xffffffffu, ssum, o);
    int col = cand[b * KCAND + i];
    out[(size_t)b * N_ENT + col] = sc;
    out[(size_t)MENT * N_ENT + (size_t)b * N_ENT + col] = e / es;
    out[(size_t)2 * MENT * N_ENT + (size_t)b * N_ENT + col] = sc / ssum;
}

/* ------------------------------- launcher ---------------------------------- */
extern "C" void kernel_launch(void* const* d_in, const int* in_sizes, int n_in,
                              void* d_out, int out_size) {
    const int*   title  = (const int*)d_in[0];
    const int*   body   = (const int*)d_in[1];
    const int*   ctx    = (const int*)d_in[3];
    const int*   doc    = (const int*)d_in[4];
    const int*   cand   = (const int*)d_in[5];
    const float* emb    = (const float*)d_in[6];
    const float* conv_w = (const float*)d_in[7];
    const float* conv_b = (const float*)d_in[8];
    const float* Wih_f  = (const float*)d_in[9];
    const float* Whh_f  = (const float*)d_in[10];
    const float* bih_f  = (const float*)d_in[11];
    const float* bhh_f  = (const float*)d_in[12];
    const float* Wih_b  = (const float*)d_in[13];
    const float* Whh_b  = (const float*)d_in[14];
    const float* bih_b  = (const float*)d_in[15];
    const float* bhh_b  = (const float*)d_in[16];
    const float* wc  = (const float*)d_in[17];
    const float* bc  = (const float*)d_in[18];
    const float* wq  = (const float*)d_in[19];
    const float* bq  = (const float*)d_in[20];
    const float* wcq = (const float*)d_in[21];
    const float* bcq = (const float*)d_in[22];
    const float* wz  = (const float*)d_in[23];
    const float* bz  = (const float*)d_in[24];
    const float* wp1 = (const float*)d_in[25];
    const float* bp1 = (const float*)d_in[26];
    const float* wp2 = (const float*)d_in[27];
    const float* bp2 = (const float*)d_in[28];
    float* out = (float*)d_out;
    (void)in_sizes; (void)n_in; (void)out_size;

    float *pT, *pB, *pF, *pWT, *pPre;
    cudaGetSymbolAddress((void**)&pT, d_T);
    cudaGetSymbolAddress((void**)&pB, d_Bmat);
    cudaGetSymbolAddress((void**)&pF, d_F);
    cudaGetSymbolAddress((void**)&pWT, d_WihT);
    cudaGetSymbolAddress((void**)&pPre, d_preAll);

    /* 0-2: cheap transposes needed by the table GEMM + pre-GEMM */
    {
        int n = CCS * EMB * WIN;
        transpose_convw<<<(n + 255) / 256, 256>>>(conv_w);
    }
    {
        int n = G4 * CCS;
        transpose_wih<<<(n + 255) / 256, 256>>>(Wih_f, 0);
        transpose_wih<<<(n + 255) / 256, 256>>>(Wih_b, 1);
    }

    /* 3: token table T = emb @ Bmat : [5053 x 2560], K=300  (profiled slot) */
    sgemm2<<<dim3((WIN * CCS) / 128, (VOCAB + 127) / 128), 256>>>(
        emb, pB, pT, VOCAB, WIN * CCS, EMB);

    /* 4-5: Whh transposes + row index table (independent of conv) */
    {
        int n = G4 * HH;
        transpose_whh<<<(n + 255) / 256, 256>>>(Whh_f, 0);
        transpose_whh<<<(n + 255) / 256, 256>>>(Whh_b, 1);
    }
    {
        int n = NSEQ * TT;
        build_rowidx<<<(n + 255) / 256, 256>>>(cand);
    }

    /* 6: char-CNN features (merged, doc+body first) */
    conv_all<<<1 + N_ENT + MENT + N_ENT, 256>>>(title, body, ctx, doc, conv_b);

    /* 7: pre-activations on UNIQUE rows, both directions: [4161 x 1024], K=512 */
    sgemm2<<<dim3(GCAT / 128, (NFEAT + 127) / 128), 256>>>(
        pF, pWT, pPre, NFEAT, GCAT, CCS);

    /* 8: recurrence (gathers pre rows) */
    lstm_kernel<<<dim3((NSEQ + 3) / 4, 2), 512>>>(bih_f, bhh_f, bih_b, bhh_b);

    /* 9: BiDAF attention + projection -> p1/p2 */
    att_kernel<<<dim3(MENT, 2), 256>>>(wc, bc, wq, bq, wcq, bcq, wz, bz);

    /* 10-11: score, softmax, sum-normalize, scatter */
    {
        int n = 3 * MENT * N_ENT;
        zero_kernel<<<(n + 255) / 256, 256>>>(out, n);
    }
    score_kernel<<<MENT, KCAND>>>(cand, wp1, bp1, wp2, bp2, out);
}

// round 5
// speedup vs baseline: 1.6166x; 1.1423x over previous
#include <cuda_runtime.h>
#include <math.h>
#include <stddef.h>

#define N_ENT 2048
#define MENT  64
#define KCAND 32
#define LT 32
#define LB 128
#define LC 128
#define LD 512
#define VOCAB 5053
#define VOCABP 5120            /* padded to 128 */
#define EMB 300
#define EMBP 304               /* padded to 16 */
#define HDIM 256
#define HH 128
#define CCS 512
#define WIN 5
#define NSEQ 193
#define TT 32
#define G4 512
#define GCAT 1024
#define NFEAT 4161
#define NFEATP 4224            /* padded to 128 */
#define WNC (WIN * CCS)        /* 2560 */
#define WCACHE 96              /* Whh rows cached in smem */

typedef unsigned long long ull;

/* ------------------------- scratch (device globals) ------------------------ */
__device__ float d_T[(size_t)VOCABP * WNC];           /* [v][w*512+c] */
__device__ float d_Bmat[EMBP * WNC];                  /* padded rows zeroed */
__device__ float d_embP[VOCABP * EMBP];
__device__ float d_F[NFEATP * CCS];                   /* pad rows stay 0 (.bss) */
__device__ float d_WihT[CCS * GCAT];
__device__ float d_preAll[(size_t)NFEATP * GCAT];
__device__ int   d_rowIdx[NSEQ * TT];
__device__ float d_WhhT_f[HH * G4];
__device__ float d_WhhT_b[HH * G4];
__device__ float d_Hcat[NSEQ * TT * HDIM];
__device__ float d_p[2 * MENT * KCAND];

__device__ __forceinline__ float sigm(float x) { return 1.f / (1.f + expf(-x)); }

__device__ __forceinline__ void fma2(ull &d, ull a, ull b) {
    asm("fma.rn.f32x2 %0, %1, %2, %0;" : "+l"(d) : "l"(a), "l"(b));
}
__device__ __forceinline__ ull pack2(float lo, float hi) {
    ull r; asm("mov.b64 %0, {%1, %2};" : "=l"(r) : "f"(lo), "f"(hi)); return r;
}
__device__ __forceinline__ float2 unpack2(ull v) {
    float2 f; asm("mov.b64 {%0, %1}, %2;" : "=f"(f.x), "=f"(f.y) : "l"(v)); return f;
}

/* ------------------------------ prep kernel -------------------------------- */
#define PN1 (CCS * EMB * WIN)          /* 768000  Bmat transpose */
#define PN1B (4 * WNC)                 /* 10240   Bmat pad rows 300..303 */
#define PN2 (VOCABP * EMBP)            /* 1556480 embP fill */
#define PN3 (2 * G4 * CCS)             /* 524288  WihT */
#define PN4 (2 * G4 * HH)              /* 131072  WhhT */
#define PN5 (NSEQ * TT)                /* 6176    rowIdx */
#define PTOT (PN1 + PN1B + PN2 + PN3 + PN4 + PN5)

__global__ void prep_kernel(const float* __restrict__ emb,
                            const float* __restrict__ conv_w,
                            const float* __restrict__ Wih_f, const float* __restrict__ Wih_b,
                            const float* __restrict__ Whh_f, const float* __restrict__ Whh_b,
                            const int* __restrict__ cand) {
    int idx = blockIdx.x * 256 + threadIdx.x;
    if (idx < PN1) {
        int c = idx / (EMB * WIN);
        int rem = idx % (EMB * WIN);
        int e = rem / WIN;
        int w = rem % WIN;
        d_Bmat[e * WNC + w * CCS + c] = conv_w[idx];
        return;
    }
    idx -= PN1;
    if (idx < PN1B) { d_Bmat[EMB * WNC + idx] = 0.f; return; }
    idx -= PN1B;
    if (idx < PN2) {
        int r = idx / EMBP, c = idx % EMBP;
        d_embP[idx] = (r < VOCAB && c < EMB) ? emb[r * EMB + c] : 0.f;
        return;
    }
    idx -= PN2;
    if (idx < PN3) {
        int dir = idx / (G4 * CCS);
        int rem = idx % (G4 * CCS);
        int g = rem / CCS, k = rem % CCS;
        d_WihT[k * GCAT + dir * G4 + g] = (dir ? Wih_b : Wih_f)[rem];
        return;
    }
    idx -= PN3;
    if (idx < PN4) {
        int dir = idx / (G4 * HH);
        int rem = idx % (G4 * HH);
        int g = rem / HH, j = rem % HH;
        float* dst = dir ? d_WhhT_b : d_WhhT_f;
        dst[j * G4 + g] = (dir ? Whh_b : Whh_f)[rem];
        return;
    }
    idx -= PN4;
    if (idx < PN5) {
        int seq = idx / TT, t = idx % TT;
        int r;
        if (seq < 64)       r = cand[seq * TT + t];
        else if (seq < 128) r = 2048 + cand[(seq - 64) * TT + t];
        else if (seq < 192) r = 4096 + (seq - 128);
        else                r = 4160;
        d_rowIdx[idx] = r;
    }
}

/* ----------- fp32x2 GEMM (FFMA2), double-buffered, no guards --------------- */
/* C[M,N] = A[M,K] @ B[K,N]. M,N multiples of 128; K multiple of 16.
   256 threads, 8x8/thread, 2 CTAs/SM.                                        */
__global__ void __launch_bounds__(256, 2) sgemm_k(
        const float* __restrict__ A, const float* __restrict__ B,
        float* __restrict__ C, int N, int K, int nk) {
    __shared__ float As[2][16][132];
    __shared__ float Bs[2][16][132];
    int tid = threadIdx.x;
    int tx = tid & 15, ty = tid >> 4;
    int m0 = blockIdx.y * 128, n0 = blockIdx.x * 128;
    int aRow = tid >> 1, aK = (tid & 1) * 8;
    int bK = tid >> 4, bN = (tid & 15) * 8;
    const float* Ap = A + (size_t)(m0 + aRow) * K + aK;
    const float* Bp = B + (size_t)bK * N + n0 + bN;

    ull acc[8][4];
#pragma unroll
    for (int i = 0; i < 8; i++)
#pragma unroll
        for (int j = 0; j < 4; j++) acc[i][j] = 0ull;

    float4 ra0 = *(const float4*)(Ap);
    float4 ra1 = *(const float4*)(Ap + 4);
    float4 rb0 = *(const float4*)(Bp);
    float4 rb1 = *(const float4*)(Bp + 4);
    As[0][aK + 0][aRow] = ra0.x; As[0][aK + 1][aRow] = ra0.y;
    As[0][aK + 2][aRow] = ra0.z; As[0][aK + 3][aRow] = ra0.w;
    As[0][aK + 4][aRow] = ra1.x; As[0][aK + 5][aRow] = ra1.y;
    As[0][aK + 6][aRow] = ra1.z; As[0][aK + 7][aRow] = ra1.w;
    *(float4*)&Bs[0][bK][bN] = rb0;
    *(float4*)&Bs[0][bK][bN + 4] = rb1;
    __syncthreads();

    for (int it = 0; it < nk; it++) {
        int cur = it & 1;
        if (it + 1 < nk) {
            const float* Ap2 = Ap + (it + 1) * 16;
            const float* Bp2 = Bp + (size_t)(it + 1) * 16 * N;
            ra0 = *(const float4*)(Ap2);
            ra1 = *(const float4*)(Ap2 + 4);
            rb0 = *(const float4*)(Bp2);
            rb1 = *(const float4*)(Bp2 + 4);
        }
#pragma unroll
        for (int kk = 0; kk < 16; kk++) {
            float4 a0 = *(const float4*)&As[cur][kk][ty * 8];
            float4 a1 = *(const float4*)&As[cur][kk][ty * 8 + 4];
            ulonglong2 bA = *(const ulonglong2*)&Bs[cur][kk][tx * 8];
            ulonglong2 bB = *(const ulonglong2*)&Bs[cur][kk][tx * 8 + 4];
            ull bp[4] = {bA.x, bA.y, bB.x, bB.y};
            float rav[8] = {a0.x, a0.y, a0.z, a0.w, a1.x, a1.y, a1.z, a1.w};
            ull ad[8];
#pragma unroll
            for (int i = 0; i < 8; i++) ad[i] = pack2(rav[i], rav[i]);
#pragma unroll
            for (int i = 0; i < 8; i++)
#pragma unroll
                for (int jp = 0; jp < 4; jp++) fma2(acc[i][jp], ad[i], bp[jp]);
        }
        if (it + 1 < nk) {
            int nxt = cur ^ 1;
            As[nxt][aK + 0][aRow] = ra0.x; As[nxt][aK + 1][aRow] = ra0.y;
            As[nxt][aK + 2][aRow] = ra0.z; As[nxt][aK + 3][aRow] = ra0.w;
            As[nxt][aK + 4][aRow] = ra1.x; As[nxt][aK + 5][aRow] = ra1.y;
            As[nxt][aK + 6][aRow] = ra1.z; As[nxt][aK + 7][aRow] = ra1.w;
            *(float4*)&Bs[nxt][bK][bN] = rb0;
            *(float4*)&Bs[nxt][bK][bN + 4] = rb1;
            __syncthreads();
        }
    }
#pragma unroll
    for (int i = 0; i < 8; i++) {
        int m = m0 + ty * 8 + i;
#pragma unroll
        for (int jp = 0; jp < 4; jp++) {
            float2 f = unpack2(acc[i][jp]);
            *(float2*)&C[(size_t)m * N + n0 + tx * 8 + 2 * jp] = f;
        }
    }
}

/* -------------------- conv via token table + maxpool ----------------------- */
__global__ void __launch_bounds__(256) conv_all(
        const int* __restrict__ title, const int* __restrict__ body,
        const int* __restrict__ ctx, const int* __restrict__ doc,
        const float* __restrict__ bias) {
    int blk = blockIdx.x;
    const int* toks; int L; int row;
    if (blk == 0)          { toks = doc;   L = LD; row = 4160; }
    else if (blk <= 2048)  { toks = body + (size_t)(blk - 1) * LB;    L = LB; row = 2048 + blk - 1; }
    else if (blk <= 2112)  { toks = ctx + (size_t)(blk - 2049) * LC;  L = LC; row = 4096 + blk - 2049; }
    else                   { toks = title + (size_t)(blk - 2113) * LT; L = LT; row = blk - 2113; }
    int c2 = threadIdx.x;
    __shared__ int st[LD];
    for (int i = c2; i < L; i += 256) st[i] = toks[i];
    __syncthreads();
    float2 b = *(const float2*)&bias[2 * c2];
    float2 m = make_float2(0.f, 0.f);
    int P = L - WIN + 1;
    for (int p = 0; p < P; p++) {
        float2 acc = b;
#pragma unroll
        for (int w = 0; w < WIN; w++) {
            int v = st[p + w];
            float2 tv = *(const float2*)&d_T[((size_t)v * WIN + w) * CCS + 2 * c2];
            acc.x += tv.x; acc.y += tv.y;
        }
        m.x = fmaxf(m.x, acc.x);
        m.y = fmaxf(m.y, acc.y);
    }
    *(float2*)&d_F[(size_t)row * CCS + 2 * c2] = m;
}

/* ----------------------------- LSTM recurrence ----------------------------- */
/* grid (49, 2), 512 threads. 4 seqs/block/dir. First WCACHE Whh rows cached
   in dynamic smem (192KB), rest streamed from L2.                            */
__global__ void __launch_bounds__(512) lstm_kernel(
        const float* __restrict__ bih_f, const float* __restrict__ bhh_f,
        const float* __restrict__ bih_b, const float* __restrict__ bhh_b) {
    extern __shared__ float sW[];     /* [WCACHE][G4] */
    int dir = blockIdx.y;
    int s0 = blockIdx.x * 4;
    const float* WT = dir ? d_WhhT_b : d_WhhT_f;
    int g = threadIdx.x;
    float bias = dir ? (bih_b[g] + bhh_b[g]) : (bih_f[g] + bhh_f[g]);
    __shared__ float shT[HH][4];
    __shared__ float sg[4][G4];
    __shared__ int ridx[4][TT];
    int so = g >> 7, d = g & 127;
    float creg = 0.f;
    shT[d][so] = 0.f;
    for (int i = g; i < WCACHE * G4; i += 512) sW[i] = WT[i];
    for (int i = g; i < 4 * TT; i += 512) {
        int s = i >> 5, t = i & 31;
        int seq = s0 + s; if (seq >= NSEQ) seq = NSEQ - 1;
        ridx[s][t] = d_rowIdx[seq * TT + t];
    }
    __syncthreads();
    int nv = NSEQ - s0; if (nv > 4) nv = 4;
    const float* preBase = d_preAll + dir * G4 + g;
    for (int step = 0; step < TT; step++) {
        int t = dir ? (TT - 1 - step) : step;
        float p0 = preBase[(size_t)ridx[0][t] * GCAT] + bias;
        float p1 = preBase[(size_t)ridx[1][t] * GCAT] + bias;
        float p2 = preBase[(size_t)ridx[2][t] * GCAT] + bias;
        float p3 = preBase[(size_t)ridx[3][t] * GCAT] + bias;
        ull a01 = pack2(p0, p1);
        ull a23 = pack2(p2, p3);
#pragma unroll 8
        for (int j = 0; j < WCACHE; j++) {
            float wv = sW[j * G4 + g];
            ulonglong2 h2 = *(const ulonglong2*)&shT[j][0];
            ull wd = pack2(wv, wv);
            fma2(a01, wd, h2.x);
            fma2(a23, wd, h2.y);
        }
#pragma unroll 8
        for (int j = WCACHE; j < HH; j++) {
            float wv = __ldg(WT + (size_t)j * G4 + g);
            ulonglong2 h2 = *(const ulonglong2*)&shT[j][0];
            ull wd = pack2(wv, wv);
            fma2(a01, wd, h2.x);
            fma2(a23, wd, h2.y);
        }
        float2 f01 = unpack2(a01);
        float2 f23 = unpack2(a23);
        sg[0][g] = f01.x; sg[1][g] = f01.y; sg[2][g] = f23.x; sg[3][g] = f23.y;
        __syncthreads();
        if (so < nv) {
            float iv = sg[so][d];
            float fv = sg[so][d + HH];
            float gv = sg[so][d + 2 * HH];
            float ov = sg[so][d + 3 * HH];
            float cn = sigm(fv) * creg + sigm(iv) * tanhf(gv);
            float hn = sigm(ov) * tanhf(cn);
            creg = cn;
            shT[d][so] = hn;
            d_Hcat[((size_t)(s0 + so) * TT + t) * HDIM + dir * HH + d] = hn;
        }
        __syncthreads();
    }
}

/* ------------------------------ BiDAF + score ------------------------------ */
__global__ void att_kernel(const float* __restrict__ wc, const float* __restrict__ bc,
                           const float* __restrict__ wq, const float* __restrict__ bq,
                           const float* __restrict__ wcq, const float* __restrict__ bcq,
                           const float* __restrict__ wz, const float* __restrict__ bz) {
    int b = blockIdx.x;
    int pair = blockIdx.y;
    int tid = threadIdx.x;
    int cseq = pair ? 192 : 128 + b;
    int qseq = pair ? 64 + b : b;
    const float* Cg = d_Hcat + (size_t)cseq * TT * HDIM;
    const float* Qg = d_Hcat + (size_t)qseq * TT * HDIM;
    __shared__ float CS[TT * HDIM];
    __shared__ float S[TT * TT];
    __shared__ float Aw[TT * TT];
    __shared__ float CD[TT], QD[TT], SMX[TT], BV[TT];
    __shared__ float Q2C[HDIM];
    __shared__ float RED[8];
    for (int i = tid; i < TT * HDIM; i += 256) CS[i] = Cg[i];
    __syncthreads();
    if (tid < TT) {
        float s = 0.f;
        const float* crow = CS + tid * HDIM;
        for (int d = 0; d < HDIM; d++) s += crow[d] * wc[d];
        CD[tid] = s;
    } else if (tid < 2 * TT) {
        int j = tid - TT;
        float s = 0.f;
        const float* qrow = Qg + (size_t)j * HDIM;
        for (int d = 0; d < HDIM; d++) s += qrow[d] * wq[d];
        QD[j] = s;
    }
    __syncthreads();
    float bsum = bc[0] + bq[0] + bcq[0];
#pragma unroll
    for (int r = 0; r < 4; r++) {
        int pi = tid * 4 + r;
        int i = pi >> 5, j = pi & 31;
        const float* crow = CS + i * HDIM;
        const float* qrow = Qg + (size_t)j * HDIM;
        float s = 0.f;
        for (int d = 0; d < HDIM; d++) s += crow[d] * qrow[d] * wcq[d];
        S[pi] = s + CD[i] + QD[j] + bsum;
    }
    __syncthreads();
    int lane = tid & 31, warp = tid >> 5;
    for (int i = warp; i < TT; i += 8) {
        float v = S[i * 32 + lane];
        float mx = v;
        for (int o = 16; o; o >>= 1) mx = fmaxf(mx, __shfl_xor_sync(0xffffffffu, mx, o));
        float e = expf(v - mx);
        float sm = e;
        for (int o = 16; o; o >>= 1) sm += __shfl_xor_sync(0xffffffffu, sm, o);
        Aw[i * 32 + lane] = e / sm;
        if (lane == 0) SMX[i] = mx;
    }
    __syncthreads();
    if (warp == 0) {
        float v = SMX[lane];
        float mx = v;
        for (int o = 16; o; o >>= 1) mx = fmaxf(mx, __shfl_xor_sync(0xffffffffu, mx, o));
        float e = expf(v - mx);
        float sm = e;
        for (int o = 16; o; o >>= 1) sm += __shfl_xor_sync(0xffffffffu, sm, o);
        BV[lane] = e / sm;
    }
    __syncthreads();
    {
        float s = 0.f;
        for (int i = 0; i < TT; i++) s += BV[i] * CS[i * HDIM + tid];
        Q2C[tid] = s;
    }
    __syncthreads();
    float bzv = bz[0];
    for (int i = 0; i < TT; i++) {
        int d = tid;
        float c2q = 0.f;
        for (int j = 0; j < TT; j++) c2q += Aw[i * 32 + j] * Qg[(size_t)j * HDIM + d];
        float cv = CS[i * HDIM + d];
        float term = cv * wz[d] + c2q * wz[HDIM + d] + cv * c2q * wz[2 * HDIM + d]
                   + cv * Q2C[d] * wz[3 * HDIM + d];
        for (int o = 16; o; o >>= 1) term += __shfl_xor_sync(0xffffffffu, term, o);
        if (lane == 0) RED[warp] = term;
        __syncthreads();
        if (tid == 0) {
            float tot = 0.f;
            for (int w2 = 0; w2 < 8; w2++) tot += RED[w2];
            d_p[(pair * MENT + b) * KCAND + i] = tot + bzv;
        }
        __syncthreads();
    }
}

__global__ void zero_kernel(float* __restrict__ out, int n) {
    int idx = blockIdx.x * blockDim.x + threadIdx.x;
    if (idx < n) out[idx] = 0.f;
}

__global__ void score_kernel(const int* __restrict__ cand,
                             const float* __restrict__ wp1, const float* __restrict__ bp1,
                             const float* __restrict__ wp2, const float* __restrict__ bp2,
                             float* __restrict__ out) {
    int b = blockIdx.x, i = threadIdx.x;
    float p1 = d_p[(0 * MENT + b) * KCAND + i];
    float p2 = d_p[(1 * MENT + b) * KCAND + i];
    float sc = wp1[0] * p1 + bp1[0] + wp2[0] * p2 + bp2[0];
    float mx = sc;
    for (int o = 16; o; o >>= 1) mx = fmaxf(mx, __shfl_xor_sync(0xffffffffu, mx, o));
    float e = expf(sc - mx);
    float es = e;
    for (int o = 16; o; o >>= 1) es += __shfl_xor_sync(0xffffffffu, es, o);
    float ssum = sc;
    for (int o = 16; o; o >>= 1) ssum += __shfl_xor_sync(0xffffffffu, ssum, o);
    int col = cand[b * KCAND + i];
    out[(size_t)b * N_ENT + col] = sc;
    out[(size_t)MENT * N_ENT + (size_t)b * N_ENT + col] = e / es;
    out[(size_t)2 * MENT * N_ENT + (size_t)b * N_ENT + col] = sc / ssum;
}

/* ------------------------------- launcher ---------------------------------- */
extern "C" void kernel_launch(void* const* d_in, const int* in_sizes, int n_in,
                              void* d_out, int out_size) {
    const int*   title  = (const int*)d_in[0];
    const int*   body   = (const int*)d_in[1];
    const int*   ctx    = (const int*)d_in[3];
    const int*   doc    = (const int*)d_in[4];
    const int*   cand   = (const int*)d_in[5];
    const float* emb    = (const float*)d_in[6];
    const float* conv_w = (const float*)d_in[7];
    const float* conv_b = (const float*)d_in[8];
    const float* Wih_f  = (const float*)d_in[9];
    const float* Whh_f  = (const float*)d_in[10];
    const float* bih_f  = (const float*)d_in[11];
    const float* bhh_f  = (const float*)d_in[12];
    const float* Wih_b  = (const float*)d_in[13];
    const float* Whh_b  = (const float*)d_in[14];
    const float* bih_b  = (const float*)d_in[15];
    const float* bhh_b  = (const float*)d_in[16];
    const float* wc  = (const float*)d_in[17];
    const float* bc  = (const float*)d_in[18];
    const float* wq  = (const float*)d_in[19];
    const float* bq  = (const float*)d_in[20];
    const float* wcq = (const float*)d_in[21];
    const float* bcq = (const float*)d_in[22];
    const float* wz  = (const float*)d_in[23];
    const float* bz  = (const float*)d_in[24];
    const float* wp1 = (const float*)d_in[25];
    const float* bp1 = (const float*)d_in[26];
    const float* wp2 = (const float*)d_in[27];
    const float* bp2 = (const float*)d_in[28];
    float* out = (float*)d_out;
    (void)in_sizes; (void)n_in; (void)out_size;

    float *pT, *pB, *pE, *pF, *pWT, *pPre;
    cudaGetSymbolAddress((void**)&pT, d_T);
    cudaGetSymbolAddress((void**)&pB, d_Bmat);
    cudaGetSymbolAddress((void**)&pE, d_embP);
    cudaGetSymbolAddress((void**)&pF, d_F);
    cudaGetSymbolAddress((void**)&pWT, d_WihT);
    cudaGetSymbolAddress((void**)&pPre, d_preAll);

    static int smem_set = 0;
    if (!smem_set) {
        cudaFuncSetAttribute(lstm_kernel, cudaFuncAttributeMaxDynamicSharedMemorySize,
                             WCACHE * G4 * (int)sizeof(float));
        smem_set = 1;
    }

    /* 1: all transposes / padded fills / row index table */
    prep_kernel<<<(PTOT + 255) / 256, 256>>>(emb, conv_w, Wih_f, Wih_b, Whh_f, Whh_b, cand);

    /* 2: zero output (independent) */
    {
        int n = 3 * MENT * N_ENT;
        zero_kernel<<<(n + 255) / 256, 256>>>(out, n);
    }

    /* 3: token table T = embP @ BmatP : [5120 x 2560], K=304 */
    sgemm_k<<<dim3(WNC / 128, VOCABP / 128), 256>>>(pE, pB, pT, WNC, EMBP, EMBP / 16);

    /* 4: char-CNN features */
    conv_all<<<1 + N_ENT + MENT + N_ENT, 256>>>(title, body, ctx, doc, conv_b);

    /* 5: pre-activations on unique rows: [4224 x 1024], K=512 */
    sgemm_k<<<dim3(GCAT / 128, NFEATP / 128), 256>>>(pF, pWT, pPre, GCAT, CCS, CCS / 16);

    /* 6: recurrence (profiled slot) */
    lstm_kernel<<<dim3((NSEQ + 3) / 4, 2), 512, WCACHE * G4 * sizeof(float)>>>(
        bih_f, bhh_f, bih_b, bhh_b);

    /* 7: BiDAF attention + projection */
    att_kernel<<<dim3(MENT, 2), 256>>>(wc, bc, wq, bq, wcq, bcq, wz, bz);

    /* 8: score, softmax, sum-normalize, scatter */
    score_kernel<<<MENT, KCAND>>>(cand, wp1, bp1, wp2, bp2, out);
}